// round 4
// baseline (speedup 1.0000x reference)
#include <cuda_runtime.h>
#include <cuda_fp16.h>
#include <mma.h>
using namespace nvcuda;

#define Nn 100000
#define Ee 1600000
#define Dd 64
#define Gg 256
#define SCALE 256.0f
#define INV_SCALE (1.0f / 256.0f)

// ---- device scratch (no allocations allowed) ----
__device__ __align__(16) __half g_ha[Nn * Dd];   // X_l (fp16, x*SCALE)
__device__ __align__(16) __half g_hb[Nn * Dd];   // Y_s (fp16, (xW)*dinv*SCALE)
__device__ __align__(16) float  g_xf[Nn * Dd];   // final-layer fp32 output
__device__ int    g_deg[Nn];
__device__ int    g_rowstart[Nn];
__device__ int    g_cursor[Nn];
__device__ float  g_dinv[Nn];
__device__ int    g_col[Ee];
__device__ float  g_h[Gg * 2 * Dd];
__device__ int    g_counter;

// ---------------- CSR build ----------------
__global__ void k_init() {
    int i = blockIdx.x * blockDim.x + threadIdx.x;
    if (i < Nn) g_deg[i] = 0;
    if (i == 0) g_counter = 0;
}

__global__ void k_hist(const int4* __restrict__ dst4) {
    int e = blockIdx.x * blockDim.x + threadIdx.x;
    if (e < Ee / 4) {
        int4 d = dst4[e];
        atomicAdd(&g_deg[d.x], 1);
        atomicAdd(&g_deg[d.y], 1);
        atomicAdd(&g_deg[d.z], 1);
        atomicAdd(&g_deg[d.w], 1);
    }
}

__global__ void k_alloc() {
    int i = blockIdx.x * blockDim.x + threadIdx.x;
    if (i < Nn) {
        int d = g_deg[i];
        int rs = atomicAdd(&g_counter, d);
        g_rowstart[i] = rs;
        g_cursor[i]   = rs;
        g_dinv[i]     = rsqrtf((float)(d + 1));
    }
}

__global__ void k_scatter(const int4* __restrict__ src4, const int4* __restrict__ dst4) {
    int e = blockIdx.x * blockDim.x + threadIdx.x;
    if (e < Ee / 4) {
        int4 s = src4[e];
        int4 d = dst4[e];
        g_col[atomicAdd(&g_cursor[d.x], 1)] = s.x;
        g_col[atomicAdd(&g_cursor[d.y], 1)] = s.y;
        g_col[atomicAdd(&g_cursor[d.z], 1)] = s.z;
        g_col[atomicAdd(&g_cursor[d.w], 1)] = s.w;
    }
}

// ---------------- embedding gather: X0 = emb * SCALE (fp16) ----------------
__global__ void k_embed(const int* __restrict__ tok, const float* __restrict__ emb) {
    int t = blockIdx.x * blockDim.x + threadIdx.x;  // Nn*16 float4s
    if (t < Nn * 16) {
        int i = t >> 4;
        float4 v = ((const float4*)emb)[tok[i] * 16 + (t & 15)];
        __half2 h0 = __floats2half2_rn(v.x * SCALE, v.y * SCALE);
        __half2 h1 = __floats2half2_rn(v.z * SCALE, v.w * SCALE);
        ((__half2*)g_ha)[2 * t]     = h0;
        ((__half2*)g_ha)[2 * t + 1] = h1;
    }
}

// ---------------- tensor-core GEMM: Y_s = (X @ W) * dinv[row], fp16 out ----------------
// Block: 256 threads = 8 warps, 128 rows (16 rows/warp). Always g_ha -> g_hb.
#define XS_LD 72   // fp16 row stride (pad)
#define CS_LD 68   // fp32 row stride (pad)

__global__ void __launch_bounds__(256) k_gemm(const float* __restrict__ W) {
    __shared__ __align__(16) char sm[8 * 16 * CS_LD * 4];  // 34816 B (union)
    __half* Xs = (__half*)sm;                       // [128][72]  (18432 B)
    __half* Wh = (__half*)(sm + 128 * XS_LD * 2);   // [64][72]   (9216 B)

    int tid = threadIdx.x;
    int warp = tid >> 5, lane = tid & 31;
    int r0 = blockIdx.x * 128;

    // stage X tile (uint4 coalesced), clamp tail rows
    const uint4* __restrict__ xin4 = (const uint4*)g_ha;
    for (int t = tid; t < 128 * 8; t += 256) {
        int row = t >> 3, c = t & 7;
        int gr = min(r0 + row, Nn - 1);
        ((uint4*)Xs)[row * (XS_LD / 8) + c] = xin4[gr * 8 + c];
    }
    // convert W to fp16 smem
    for (int t = tid; t < Dd * Dd; t += 256) {
        int k = t >> 6, n = t & 63;
        Wh[k * XS_LD + n] = __float2half(W[t]);
    }
    __syncthreads();

    wmma::fragment<wmma::accumulator, 16, 16, 16, float> c[4];
#pragma unroll
    for (int j = 0; j < 4; j++) wmma::fill_fragment(c[j], 0.0f);

#pragma unroll
    for (int k = 0; k < 4; k++) {
        wmma::fragment<wmma::matrix_a, 16, 16, 16, __half, wmma::row_major> a;
        wmma::load_matrix_sync(a, Xs + (warp * 16) * XS_LD + k * 16, XS_LD);
#pragma unroll
        for (int j = 0; j < 4; j++) {
            wmma::fragment<wmma::matrix_b, 16, 16, 16, __half, wmma::row_major> bf;
            wmma::load_matrix_sync(bf, Wh + (k * 16) * XS_LD + j * 16, XS_LD);
            wmma::mma_sync(c[j], a, bf, c[j]);
        }
    }
    __syncthreads();   // everyone done reading Xs/Wh; reuse smem for C

    float* cw = (float*)sm + warp * (16 * CS_LD);
#pragma unroll
    for (int j = 0; j < 4; j++)
        wmma::store_matrix_sync(cw + j * 16, c[j], CS_LD, wmma::mem_row_major);
    __syncwarp();

    // epilogue: scale by dinv, convert fp16, store. lane -> (row, half-of-row)
    int row = lane >> 1, h = lane & 1;
    int gr = r0 + warp * 16 + row;
    if (gr < Nn) {
        float d = g_dinv[gr];
        const float* src = cw + row * CS_LD + h * 32;
        uint4* dst = (uint4*)g_hb + gr * 8 + h * 4;
#pragma unroll
        for (int q = 0; q < 4; q++) {
            float4 f0 = ((const float4*)src)[2 * q];
            float4 f1 = ((const float4*)src)[2 * q + 1];
            __half2 h0 = __floats2half2_rn(f0.x * d, f0.y * d);
            __half2 h1 = __floats2half2_rn(f0.z * d, f0.w * d);
            __half2 h2 = __floats2half2_rn(f1.x * d, f1.y * d);
            __half2 h3 = __floats2half2_rn(f1.z * d, f1.w * d);
            uint4 o;
            o.x = *(unsigned*)&h0; o.y = *(unsigned*)&h1;
            o.z = *(unsigned*)&h2; o.w = *(unsigned*)&h3;
            dst[q] = o;
        }
    }
}

// ---------------- aggregate: z = relu(dinv_i * (sum Y_s) + b), 2 nodes/warp ----------------
__device__ __forceinline__ void unpack_add(float4& a, uint2 r) {
    float2 f0 = __half22float2(*(__half2*)&r.x);
    float2 f1 = __half22float2(*(__half2*)&r.y);
    a.x += f0.x; a.y += f0.y; a.z += f1.x; a.w += f1.y;
}

__global__ void __launch_bounds__(256) k_aggr(const float* __restrict__ b, int out_mode) {
    int warp = threadIdx.x >> 5, lane = threadIdx.x & 31;
    int hw = lane >> 4;          // node within pair
    int sl = lane & 15;          // owns 4 feature cols
    int i = (blockIdx.x * 8 + warp) * 2 + hw;   // Nn = 6250*16 exactly

    const uint2* __restrict__ y2 = (const uint2*)g_hb;

    float4 acc = make_float4(0.f, 0.f, 0.f, 0.f);
    unpack_add(acc, y2[i * 16 + sl]);           // self-loop

    int rs  = g_rowstart[i];
    int cnt = g_deg[i];
    int cmax = max(cnt, __shfl_xor_sync(0xffffffffu, cnt, 16));

    for (int e = 0; e < cmax; e += 4) {
        int i0 = min(rs + e,     Ee - 1);
        int i1 = min(rs + e + 1, Ee - 1);
        int i2 = min(rs + e + 2, Ee - 1);
        int i3 = min(rs + e + 3, Ee - 1);
        int s0 = g_col[i0];
        int s1 = g_col[i1];
        int s2 = g_col[i2];
        int s3 = g_col[i3];
        uint2 r0 = y2[s0 * 16 + sl];
        uint2 r1 = y2[s1 * 16 + sl];
        uint2 r2 = y2[s2 * 16 + sl];
        uint2 r3 = y2[s3 * 16 + sl];
        if (e     < cnt) unpack_add(acc, r0);
        if (e + 1 < cnt) unpack_add(acc, r1);
        if (e + 2 < cnt) unpack_add(acc, r2);
        if (e + 3 < cnt) unpack_add(acc, r3);
    }

    float di = g_dinv[i];
    float4 bb = ((const float4*)b)[sl];

    if (out_mode == 0) {
        // store x_{l+1} * SCALE in fp16:  relu(acc*dinv + b*SCALE)
        float ox = fmaxf(fmaf(acc.x, di, bb.x * SCALE), 0.f);
        float oy = fmaxf(fmaf(acc.y, di, bb.y * SCALE), 0.f);
        float oz = fmaxf(fmaf(acc.z, di, bb.z * SCALE), 0.f);
        float ow = fmaxf(fmaf(acc.w, di, bb.w * SCALE), 0.f);
        __half2 h0 = __floats2half2_rn(ox, oy);
        __half2 h1 = __floats2half2_rn(oz, ow);
        uint2 r;
        r.x = *(unsigned*)&h0;
        r.y = *(unsigned*)&h1;
        ((uint2*)g_ha)[i * 16 + sl] = r;
    } else {
        float f = di * INV_SCALE;
        float4 o;
        o.x = fmaxf(fmaf(acc.x, f, bb.x), 0.f);
        o.y = fmaxf(fmaf(acc.y, f, bb.y), 0.f);
        o.z = fmaxf(fmaf(acc.z, f, bb.z), 0.f);
        o.w = fmaxf(fmaf(acc.w, f, bb.w), 0.f);
        ((float4*)g_xf)[i * 16 + sl] = o;
    }
}

// ---------------- graph pooling (mean + max), batch is sorted ----------------
__global__ void __launch_bounds__(128) k_pool(const int* __restrict__ batch) {
    int g = blockIdx.x;
    int lo = 0, hi = Nn;
    while (lo < hi) { int m = (lo + hi) >> 1; if (batch[m] < g) lo = m + 1; else hi = m; }
    int start = lo;
    hi = Nn;
    while (lo < hi) { int m = (lo + hi) >> 1; if (batch[m] < g + 1) lo = m + 1; else hi = m; }
    int end = lo;

    int warp = threadIdx.x >> 5, lane = threadIdx.x & 31;
    const float2* __restrict__ x2 = (const float2*)g_xf;
    float2 s  = make_float2(0.f, 0.f);
    float2 mx = make_float2(0.f, 0.f);
    for (int i = start + warp; i < end; i += 4) {
        float2 v = x2[i * 32 + lane];
        s.x += v.x; s.y += v.y;
        mx.x = fmaxf(mx.x, v.x); mx.y = fmaxf(mx.y, v.y);
    }
    __shared__ float2 ss[4][32], sm2[4][32];
    ss[warp][lane] = s; sm2[warp][lane] = mx;
    __syncthreads();
    if (warp == 0) {
        for (int w = 1; w < 4; w++) {
            s.x += ss[w][lane].x; s.y += ss[w][lane].y;
            mx.x = fmaxf(mx.x, sm2[w][lane].x); mx.y = fmaxf(mx.y, sm2[w][lane].y);
        }
        float inv = 1.f / fmaxf((float)(end - start), 1.f);
        g_h[g * 128 + 2 * lane]          = s.x * inv;
        g_h[g * 128 + 2 * lane + 1]      = s.y * inv;
        g_h[g * 128 + 64 + 2 * lane]     = mx.x;
        g_h[g * 128 + 64 + 2 * lane + 1] = mx.y;
    }
}

// ---------------- classifier head ----------------
__global__ void __launch_bounds__(64) k_cls(const float* __restrict__ Wc1,
                                            const float* __restrict__ bc1,
                                            const float* __restrict__ Wc2,
                                            const float* __restrict__ bc2,
                                            float* __restrict__ out) {
    int g = blockIdx.x, j = threadIdx.x;
    __shared__ float hs[128], hid[64];
    hs[j]      = g_h[g * 128 + j];
    hs[j + 64] = g_h[g * 128 + j + 64];
    __syncthreads();
    float acc = bc1[j];
#pragma unroll
    for (int k = 0; k < 128; k++)
        acc = fmaf(hs[k], Wc1[k * 64 + j], acc);
    hid[j] = fmaxf(acc, 0.f);
    __syncthreads();
    if (j < 2) {
        float a = bc2[j];
#pragma unroll
        for (int k = 0; k < 64; k++)
            a = fmaf(hid[k], Wc2[k * 2 + j], a);
        out[g * 2 + j] = a;
    }
}

extern "C" void kernel_launch(void* const* d_in, const int* in_sizes, int n_in,
                              void* d_out, int out_size) {
    const int*   tok   = (const int*)d_in[0];
    const int*   ei    = (const int*)d_in[1];
    const int*   batch = (const int*)d_in[2];
    const float* emb   = (const float*)d_in[3];
    const float* W0 = (const float*)d_in[4];  const float* b0 = (const float*)d_in[5];
    const float* W1 = (const float*)d_in[6];  const float* b1 = (const float*)d_in[7];
    const float* W2 = (const float*)d_in[8];  const float* b2 = (const float*)d_in[9];
    const float* Wc1 = (const float*)d_in[10]; const float* bc1 = (const float*)d_in[11];
    const float* Wc2 = (const float*)d_in[12]; const float* bc2 = (const float*)d_in[13];
    float* out = (float*)d_out;

    const int4* src4 = (const int4*)ei;
    const int4* dst4 = (const int4*)(ei + Ee);

    k_init   <<<(Nn + 255) / 256, 256>>>();
    k_hist   <<<(Ee / 4 + 255) / 256, 256>>>(dst4);
    k_alloc  <<<(Nn + 255) / 256, 256>>>();
    k_scatter<<<(Ee / 4 + 255) / 256, 256>>>(src4, dst4);
    k_embed  <<<(Nn * 16 + 255) / 256, 256>>>(tok, emb);

    const int GG = (Nn + 127) / 128;   // 782
    const int AG = Nn / 16;            // 6250

    k_gemm<<<GG, 256>>>(W0);  k_aggr<<<AG, 256>>>(b0, 0);
    k_gemm<<<GG, 256>>>(W1);  k_aggr<<<AG, 256>>>(b1, 0);
    k_gemm<<<GG, 256>>>(W2);  k_aggr<<<AG, 256>>>(b2, 1);

    k_pool<<<Gg, 128>>>(batch);
    k_cls <<<Gg, 64>>>(Wc1, bc1, Wc2, bc2, out);
}

// round 6
// speedup vs baseline: 1.4573x; 1.4573x over previous
#include <cuda_runtime.h>
#include <cuda_fp16.h>
#include <mma.h>
using namespace nvcuda;

#define Nn 100000
#define Ee 1600000
#define Dd 64
#define Gg 256
#define SCALE 256.0f
#define INV_SCALE (1.0f / 256.0f)

#define NB 592            // 148 SMs x 4 blocks -- guaranteed co-resident
#define NT 256
#define GT (NB * NT)
#define GEMM_TILES 782    // ceil(Nn / 128)
#define XS_LD 72
#define CS_LD 68
#define P4_GEMM_BLKS 148  // phase 4: blocks < this do gemm0, rest do scatter

// ---- device scratch (no allocations allowed) ----
__device__ __align__(16) __half g_ha[Nn * Dd];   // X_l (fp16, x*SCALE)
__device__ __align__(16) __half g_hb[Nn * Dd];   // Y_s (fp16, (xW)*dinv*SCALE)
__device__ __align__(16) float  g_xf[Nn * Dd];   // final fp32 output
__device__ int      g_deg[Nn];
__device__ int      g_rowstart[Nn];
__device__ int      g_cursor[Nn];
__device__ float    g_dinv[Nn];
__device__ int      g_col[Ee];
__device__ int      g_counter;
__device__ unsigned g_count;            // barrier arrival counter (returns to 0)
__device__ volatile unsigned g_sense;   // barrier sense (even #bars -> returns to 0)

// ---------------- grid-wide sense-reversing barrier ----------------
__device__ __forceinline__ void gsync(unsigned& ls) {
    __syncthreads();
    if (threadIdx.x == 0) {
        ls ^= 1u;
        __threadfence();                      // release prior writes
        if (atomicAdd(&g_count, 1u) == NB - 1u) {
            g_count = 0u;                     // nobody polls count -> safe
            __threadfence();
            g_sense = ls;                     // release
        } else {
            while (g_sense != ls) { __nanosleep(64); }
            __threadfence();                  // acquire
        }
    }
    __syncthreads();
}

// ---------------- tensor-core GEMM phase: g_hb = (g_ha @ W) * dinv[row] ----------------
__device__ void gemm_phase(const float* __restrict__ W, int t0, int tstride, char* sm) {
    __half* Xs = (__half*)sm;                       // [128][72]
    __half* Wh = (__half*)(sm + 128 * XS_LD * 2);   // [64][72]
    int tid = threadIdx.x, warp = tid >> 5, lane = tid & 31;
    const uint4* __restrict__ xin4 = (const uint4*)g_ha;

    for (int tile = t0; tile < GEMM_TILES; tile += tstride) {
        int r0 = tile * 128;
        for (int t = tid; t < 128 * 8; t += NT) {
            int row = t >> 3, c = t & 7;
            int gr = min(r0 + row, Nn - 1);
            ((uint4*)Xs)[row * (XS_LD / 8) + c] = xin4[gr * 8 + c];
        }
        for (int t = tid; t < Dd * Dd; t += NT) {
            int k = t >> 6, n = t & 63;
            Wh[k * XS_LD + n] = __float2half(W[t]);
        }
        __syncthreads();

        wmma::fragment<wmma::accumulator, 16, 16, 16, float> c[4];
#pragma unroll
        for (int j = 0; j < 4; j++) wmma::fill_fragment(c[j], 0.0f);
#pragma unroll
        for (int k = 0; k < 4; k++) {
            wmma::fragment<wmma::matrix_a, 16, 16, 16, __half, wmma::row_major> a;
            wmma::load_matrix_sync(a, Xs + (warp * 16) * XS_LD + k * 16, XS_LD);
#pragma unroll
            for (int j = 0; j < 4; j++) {
                wmma::fragment<wmma::matrix_b, 16, 16, 16, __half, wmma::row_major> bf;
                wmma::load_matrix_sync(bf, Wh + (k * 16) * XS_LD + j * 16, XS_LD);
                wmma::mma_sync(c[j], a, bf, c[j]);
            }
        }
        __syncthreads();                        // reuse smem for C

        float* cw = (float*)sm + warp * (16 * CS_LD);
#pragma unroll
        for (int j = 0; j < 4; j++)
            wmma::store_matrix_sync(cw + j * 16, c[j], CS_LD, wmma::mem_row_major);
        __syncwarp();

        int row = lane >> 1, h = lane & 1;
        int gr = r0 + warp * 16 + row;
        if (gr < Nn) {
            float d = g_dinv[gr];
            const float* src = cw + row * CS_LD + h * 32;
            uint4* dst = (uint4*)g_hb + gr * 8 + h * 4;
#pragma unroll
            for (int q = 0; q < 4; q++) {
                float4 f0 = ((const float4*)src)[2 * q];
                float4 f1 = ((const float4*)src)[2 * q + 1];
                __half2 h0 = __floats2half2_rn(f0.x * d, f0.y * d);
                __half2 h1 = __floats2half2_rn(f0.z * d, f0.w * d);
                __half2 h2 = __floats2half2_rn(f1.x * d, f1.y * d);
                __half2 h3 = __floats2half2_rn(f1.z * d, f1.w * d);
                uint4 o;
                o.x = *(unsigned*)&h0; o.y = *(unsigned*)&h1;
                o.z = *(unsigned*)&h2; o.w = *(unsigned*)&h3;
                dst[q] = o;
            }
        }
        __syncthreads();                        // protect smem before next tile
    }
}

// ---------------- aggregate phase: relu(dinv_i * sum(g_hb) + b) ----------------
__device__ __forceinline__ void unpack_add(float4& a, uint2 r) {
    float2 f0 = __half22float2(*(__half2*)&r.x);
    float2 f1 = __half22float2(*(__half2*)&r.y);
    a.x += f0.x; a.y += f0.y; a.z += f1.x; a.w += f1.y;
}

__device__ void aggr_phase(const float* __restrict__ b, int out_mode) {
    int warp = threadIdx.x >> 5, lane = threadIdx.x & 31;
    int hw = lane >> 4;
    int sl = lane & 15;
    const uint2* __restrict__ y2 = (const uint2*)g_hb;
    float4 bb = ((const float4*)b)[sl];
    int w0 = blockIdx.x * 8 + warp;

    for (int p = w0; p < Nn / 2; p += NB * 8) {
        int i = 2 * p + hw;

        float4 acc = make_float4(0.f, 0.f, 0.f, 0.f);
        unpack_add(acc, y2[i * 16 + sl]);           // self-loop

        int rs  = g_rowstart[i];
        int cnt = g_deg[i];
        int cmax = max(cnt, __shfl_xor_sync(0xffffffffu, cnt, 16));

        for (int e = 0; e < cmax; e += 4) {
            int i0 = min(rs + e,     Ee - 1);
            int i1 = min(rs + e + 1, Ee - 1);
            int i2 = min(rs + e + 2, Ee - 1);
            int i3 = min(rs + e + 3, Ee - 1);
            int s0 = g_col[i0];
            int s1 = g_col[i1];
            int s2 = g_col[i2];
            int s3 = g_col[i3];
            uint2 r0 = y2[s0 * 16 + sl];
            uint2 r1 = y2[s1 * 16 + sl];
            uint2 r2 = y2[s2 * 16 + sl];
            uint2 r3 = y2[s3 * 16 + sl];
            if (e     < cnt) unpack_add(acc, r0);
            if (e + 1 < cnt) unpack_add(acc, r1);
            if (e + 2 < cnt) unpack_add(acc, r2);
            if (e + 3 < cnt) unpack_add(acc, r3);
        }

        float di = g_dinv[i];
        if (out_mode == 0) {
            float ox = fmaxf(fmaf(acc.x, di, bb.x * SCALE), 0.f);
            float oy = fmaxf(fmaf(acc.y, di, bb.y * SCALE), 0.f);
            float oz = fmaxf(fmaf(acc.z, di, bb.z * SCALE), 0.f);
            float ow = fmaxf(fmaf(acc.w, di, bb.w * SCALE), 0.f);
            __half2 h0 = __floats2half2_rn(ox, oy);
            __half2 h1 = __floats2half2_rn(oz, ow);
            uint2 r;
            r.x = *(unsigned*)&h0;
            r.y = *(unsigned*)&h1;
            ((uint2*)g_ha)[i * 16 + sl] = r;
        } else {
            float f = di * INV_SCALE;
            float4 o;
            o.x = fmaxf(fmaf(acc.x, f, bb.x), 0.f);
            o.y = fmaxf(fmaf(acc.y, f, bb.y), 0.f);
            o.z = fmaxf(fmaf(acc.z, f, bb.z), 0.f);
            o.w = fmaxf(fmaf(acc.w, f, bb.w), 0.f);
            ((float4*)g_xf)[i * 16 + sl] = o;
        }
    }
}

// ---------------- pool (mean+max) + classifier, one block per graph ----------------
__device__ void pool_cls(const int* __restrict__ batch,
                         const float* __restrict__ Wc1, const float* __restrict__ bc1,
                         const float* __restrict__ Wc2, const float* __restrict__ bc2,
                         float* __restrict__ out, char* sm) {
    int g = blockIdx.x;
    int lo = 0, hi = Nn;
    while (lo < hi) { int m = (lo + hi) >> 1; if (batch[m] < g) lo = m + 1; else hi = m; }
    int start = lo;
    hi = Nn;
    while (lo < hi) { int m = (lo + hi) >> 1; if (batch[m] < g + 1) lo = m + 1; else hi = m; }
    int end = lo;

    int warp = threadIdx.x >> 5, lane = threadIdx.x & 31;
    const float2* __restrict__ x2 = (const float2*)g_xf;
    float2 s  = make_float2(0.f, 0.f);
    float2 mx = make_float2(0.f, 0.f);
    for (int i = start + warp; i < end; i += 8) {
        float2 v = x2[i * 32 + lane];
        s.x += v.x; s.y += v.y;
        mx.x = fmaxf(mx.x, v.x); mx.y = fmaxf(mx.y, v.y);
    }
    float*  hs  = (float*)sm;                      // [128]
    float2* ss  = (float2*)(sm + 512);             // [8][32]
    float2* sm2 = (float2*)(sm + 512 + 2048);      // [8][32]
    float*  hid = (float*)(sm + 512 + 4096);       // [64]
    ss[warp * 32 + lane] = s;
    sm2[warp * 32 + lane] = mx;
    __syncthreads();
    if (warp == 0) {
        for (int w = 1; w < 8; w++) {
            float2 a = ss[w * 32 + lane], m = sm2[w * 32 + lane];
            s.x += a.x; s.y += a.y;
            mx.x = fmaxf(mx.x, m.x); mx.y = fmaxf(mx.y, m.y);
        }
        float inv = 1.f / fmaxf((float)(end - start), 1.f);
        hs[2 * lane]          = s.x * inv;
        hs[2 * lane + 1]      = s.y * inv;
        hs[64 + 2 * lane]     = mx.x;
        hs[64 + 2 * lane + 1] = mx.y;
    }
    __syncthreads();
    int j = threadIdx.x;
    if (j < 64) {
        float acc = bc1[j];
#pragma unroll
        for (int k = 0; k < 128; k++)
            acc = fmaf(hs[k], Wc1[k * 64 + j], acc);
        hid[j] = fmaxf(acc, 0.f);
    }
    __syncthreads();
    if (j < 2) {
        float a = bc2[j];
#pragma unroll
        for (int k = 0; k < 64; k++)
            a = fmaf(hid[k], Wc2[k * 2 + j], a);
        out[g * 2 + j] = a;
    }
    __syncthreads();
}

// ---------------- the one persistent kernel ----------------
__global__ void __launch_bounds__(NT, 4) k_all(
    const int* __restrict__ tok, const int* __restrict__ ei,
    const int* __restrict__ batch, const float* __restrict__ emb,
    const float* __restrict__ W0, const float* __restrict__ b0,
    const float* __restrict__ W1, const float* __restrict__ b1,
    const float* __restrict__ W2, const float* __restrict__ b2,
    const float* __restrict__ Wc1, const float* __restrict__ bc1,
    const float* __restrict__ Wc2, const float* __restrict__ bc2,
    float* __restrict__ out)
{
    __shared__ __align__(16) char smbuf[34816];
    unsigned ls = 0;
    int gtid = blockIdx.x * NT + threadIdx.x;
    const int4* src4 = (const int4*)ei;
    const int4* dst4 = (const int4*)(ei + Ee);

    // ---- P1: zero deg + reset counter + embed (X0 = emb*SCALE fp16) ----
    for (int i = gtid; i < Nn; i += GT) g_deg[i] = 0;
    if (gtid == 0) g_counter = 0;
    for (int t = gtid; t < Nn * 16; t += GT) {
        int i = t >> 4;
        float4 v = ((const float4*)emb)[tok[i] * 16 + (t & 15)];
        __half2 h0 = __floats2half2_rn(v.x * SCALE, v.y * SCALE);
        __half2 h1 = __floats2half2_rn(v.z * SCALE, v.w * SCALE);
        ((__half2*)g_ha)[2 * t]     = h0;
        ((__half2*)g_ha)[2 * t + 1] = h1;
    }
    gsync(ls);   // 1

    // ---- P2: degree histogram ----
    for (int e = gtid; e < Ee / 4; e += GT) {
        int4 d = dst4[e];
        atomicAdd(&g_deg[d.x], 1);
        atomicAdd(&g_deg[d.y], 1);
        atomicAdd(&g_deg[d.z], 1);
        atomicAdd(&g_deg[d.w], 1);
    }
    gsync(ls);   // 2

    // ---- P3: row allocation + dinv ----
    for (int i = gtid; i < Nn; i += GT) {
        int d = g_deg[i];
        int rs = atomicAdd(&g_counter, d);
        g_rowstart[i] = rs;
        g_cursor[i]   = rs;
        g_dinv[i]     = rsqrtf((float)(d + 1));
    }
    gsync(ls);   // 3

    // ---- P4: scatter (444 blocks) CONCURRENT with gemm0 (148 blocks) ----
    if (blockIdx.x < P4_GEMM_BLKS) {
        gemm_phase(W0, blockIdx.x, P4_GEMM_BLKS, smbuf);
    } else {
        int lt = (blockIdx.x - P4_GEMM_BLKS) * NT + threadIdx.x;
        int LS = (NB - P4_GEMM_BLKS) * NT;
        for (int e = lt; e < Ee / 4; e += LS) {
            int4 s = src4[e];
            int4 d = dst4[e];
            g_col[atomicAdd(&g_cursor[d.x], 1)] = s.x;
            g_col[atomicAdd(&g_cursor[d.y], 1)] = s.y;
            g_col[atomicAdd(&g_cursor[d.z], 1)] = s.z;
            g_col[atomicAdd(&g_cursor[d.w], 1)] = s.w;
        }
    }
    gsync(ls);   // 4

    aggr_phase(b0, 0);                       gsync(ls);   // 5
    gemm_phase(W1, blockIdx.x, NB, smbuf);   gsync(ls);   // 6
    aggr_phase(b1, 0);                       gsync(ls);   // 7
    gemm_phase(W2, blockIdx.x, NB, smbuf);   gsync(ls);   // 8
    aggr_phase(b2, 1);                       gsync(ls);   // 9

    // ---- P10: pool + classifier ----
    if (blockIdx.x < Gg)
        pool_cls(batch, Wc1, bc1, Wc2, bc2, out, smbuf);
    gsync(ls);   // 10 (even count -> g_sense returns to 0 for next launch)
}

extern "C" void kernel_launch(void* const* d_in, const int* in_sizes, int n_in,
                              void* d_out, int out_size) {
    const int*   tok   = (const int*)d_in[0];
    const int*   ei    = (const int*)d_in[1];
    const int*   batch = (const int*)d_in[2];
    const float* emb   = (const float*)d_in[3];
    const float* W0 = (const float*)d_in[4];  const float* b0 = (const float*)d_in[5];
    const float* W1 = (const float*)d_in[6];  const float* b1 = (const float*)d_in[7];
    const float* W2 = (const float*)d_in[8];  const float* b2 = (const float*)d_in[9];
    const float* Wc1 = (const float*)d_in[10]; const float* bc1 = (const float*)d_in[11];
    const float* Wc2 = (const float*)d_in[12]; const float* bc2 = (const float*)d_in[13];
    float* out = (float*)d_out;

    k_all<<<NB, NT>>>(tok, ei, batch, emb, W0, b0, W1, b1, W2, b2,
                      Wc1, bc1, Wc2, bc2, out);
}

// round 11
// speedup vs baseline: 1.5297x; 1.0497x over previous
#include <cuda_runtime.h>
#include <cuda_fp16.h>
#include <mma.h>
using namespace nvcuda;

#define Nn 100000
#define Ee 1600000
#define Dd 64
#define Gg 256
#define SCALE 256.0f
#define INV_SCALE (1.0f / 256.0f)

#define NB 592            // 148 SMs x 4 blocks -- co-resident (64 regs, 34.8KB smem)
#define NT 256
#define GT (NB * NT)
#define GEMM_TILES 782    // ceil(Nn / 128)
#define XS_LD 72
#define CS_LD 68
#define P4_GEMM_BLKS 148  // phase 4 split: gemm0 vs scatter
#define COLSZ (Ee + 7 * Nn + 64)

// ---- device scratch ----
__device__ __align__(16) __half g_ha[Nn * Dd];         // X_l (fp16, x*SCALE)
__device__ __align__(16) __half g_hb[(Nn + 1) * Dd];   // Y_s + sentinel zero row
__device__ __align__(16) float  g_xf[Nn * Dd];         // final fp32 output
__device__ __align__(16) __half g_w[3][Dd * Dd];       // fp16 weight copies
__device__ int      g_deg[Nn];        // padded counts after alloc; zeroed at end
__device__ int      g_rowstart[Nn];
__device__ int      g_cursor[Nn];
__device__ float    g_dinv[Nn];
__device__ int      g_col[COLSZ];
__device__ int      g_counter;        // reset at end of each launch
__device__ unsigned g_count;
__device__ volatile unsigned g_sense; // even #barriers -> returns to 0

// ---------------- grid-wide sense-reversing barrier ----------------
__device__ __forceinline__ void gsync(unsigned& ls) {
    __syncthreads();
    if (threadIdx.x == 0) {
        ls ^= 1u;
        __threadfence();
        if (atomicAdd(&g_count, 1u) == NB - 1u) {
            g_count = 0u;
            __threadfence();
            g_sense = ls;
        } else {
            while (g_sense != ls) { __nanosleep(64); }
            __threadfence();
        }
    }
    __syncthreads();
}

// ---------------- tensor-core GEMM phase: g_hb = (g_ha @ W) * dinv[row] ----------------
__device__ void gemm_phase(const __half* __restrict__ Wg, int t0, int tstride, char* sm) {
    __half* Xs = (__half*)sm;                       // [128][72]
    __half* Wh = (__half*)(sm + 128 * XS_LD * 2);   // [64][72]
    int tid = threadIdx.x, warp = tid >> 5, lane = tid & 31;
    const uint4* __restrict__ xin4 = (const uint4*)g_ha;
    const uint4* __restrict__ wg4  = (const uint4*)Wg;

    for (int tile = t0; tile < GEMM_TILES; tile += tstride) {
        int r0 = tile * 128;
        for (int t = tid; t < 128 * 8; t += NT) {
            int row = t >> 3, c = t & 7;
            int gr = min(r0 + row, Nn - 1);
            ((uint4*)(Xs + row * XS_LD))[c] = xin4[gr * 8 + c];
        }
        for (int t = tid; t < 512; t += NT) {       // 64 rows x 8 uint4
            int row = t >> 3, c = t & 7;
            ((uint4*)(Wh + row * XS_LD))[c] = wg4[t];
        }
        __syncthreads();

        wmma::fragment<wmma::accumulator, 16, 16, 16, float> c[4];
#pragma unroll
        for (int j = 0; j < 4; j++) wmma::fill_fragment(c[j], 0.0f);
#pragma unroll
        for (int k = 0; k < 4; k++) {
            wmma::fragment<wmma::matrix_a, 16, 16, 16, __half, wmma::row_major> a;
            wmma::load_matrix_sync(a, Xs + (warp * 16) * XS_LD + k * 16, XS_LD);
#pragma unroll
            for (int j = 0; j < 4; j++) {
                wmma::fragment<wmma::matrix_b, 16, 16, 16, __half, wmma::row_major> bf;
                wmma::load_matrix_sync(bf, Wh + (k * 16) * XS_LD + j * 16, XS_LD);
                wmma::mma_sync(c[j], a, bf, c[j]);
            }
        }
        __syncthreads();                        // reuse smem for C

        float* cw = (float*)sm + warp * (16 * CS_LD);
#pragma unroll
        for (int j = 0; j < 4; j++)
            wmma::store_matrix_sync(cw + j * 16, c[j], CS_LD, wmma::mem_row_major);
        __syncwarp();

        int row = lane >> 1, h = lane & 1;
        int gr = r0 + warp * 16 + row;
        if (gr < Nn) {
            float d = g_dinv[gr];
            const float* src = cw + row * CS_LD + h * 32;
            uint4* dst = (uint4*)g_hb + gr * 8 + h * 4;
#pragma unroll
            for (int q = 0; q < 4; q++) {
                float4 f0 = ((const float4*)src)[2 * q];
                float4 f1 = ((const float4*)src)[2 * q + 1];
                __half2 h0 = __floats2half2_rn(f0.x * d, f0.y * d);
                __half2 h1 = __floats2half2_rn(f0.z * d, f0.w * d);
                __half2 h2 = __floats2half2_rn(f1.x * d, f1.y * d);
                __half2 h3 = __floats2half2_rn(f1.z * d, f1.w * d);
                uint4 o;
                o.x = *(unsigned*)&h0; o.y = *(unsigned*)&h1;
                o.z = *(unsigned*)&h2; o.w = *(unsigned*)&h3;
                dst[q] = o;
            }
        }
        __syncthreads();
    }
}

// ---------------- aggregate phase: relu(dinv_i * sum(g_hb) + b) ----------------
__device__ __forceinline__ void unpack_add(float4& a, uint2 r) {
    float2 f0 = __half22float2(*(__half2*)&r.x);
    float2 f1 = __half22float2(*(__half2*)&r.y);
    a.x += f0.x; a.y += f0.y; a.z += f1.x; a.w += f1.y;
}

__device__ void aggr_phase(const float* __restrict__ b, int out_mode) {
    int warp = threadIdx.x >> 5, lane = threadIdx.x & 31;
    int hw = lane >> 4;
    int sl = lane & 15;
    const uint2* __restrict__ y2 = (const uint2*)g_hb;
    float4 bb = ((const float4*)b)[sl];

    for (int p = blockIdx.x * 8 + warp; p < Nn / 2; p += NB * 8) {
        int i = 2 * p + hw;

        float4 acc = make_float4(0.f, 0.f, 0.f, 0.f);
        unpack_add(acc, y2[i * 16 + sl]);           // self-loop

        int rs = g_rowstart[i];
        int cp = g_deg[i];                          // padded to multiple of 8
        const int* __restrict__ cptr = g_col + rs;

        for (int e = 0; e < cp; e += 8) {
            int s0 = cptr[e];
            int s1 = cptr[e + 1];
            int s2 = cptr[e + 2];
            int s3 = cptr[e + 3];
            int s4 = cptr[e + 4];
            int s5 = cptr[e + 5];
            int s6 = cptr[e + 6];
            int s7 = cptr[e + 7];
            uint2 r0 = y2[s0 * 16 + sl];
            uint2 r1 = y2[s1 * 16 + sl];
            uint2 r2 = y2[s2 * 16 + sl];
            uint2 r3 = y2[s3 * 16 + sl];
            uint2 r4 = y2[s4 * 16 + sl];
            uint2 r5 = y2[s5 * 16 + sl];
            uint2 r6 = y2[s6 * 16 + sl];
            uint2 r7 = y2[s7 * 16 + sl];
            unpack_add(acc, r0);
            unpack_add(acc, r1);
            unpack_add(acc, r2);
            unpack_add(acc, r3);
            unpack_add(acc, r4);
            unpack_add(acc, r5);
            unpack_add(acc, r6);
            unpack_add(acc, r7);
        }

        float di = g_dinv[i];
        if (out_mode == 0) {
            float ox = fmaxf(fmaf(acc.x, di, bb.x * SCALE), 0.f);
            float oy = fmaxf(fmaf(acc.y, di, bb.y * SCALE), 0.f);
            float oz = fmaxf(fmaf(acc.z, di, bb.z * SCALE), 0.f);
            float ow = fmaxf(fmaf(acc.w, di, bb.w * SCALE), 0.f);
            __half2 h0 = __floats2half2_rn(ox, oy);
            __half2 h1 = __floats2half2_rn(oz, ow);
            uint2 r;
            r.x = *(unsigned*)&h0;
            r.y = *(unsigned*)&h1;
            ((uint2*)g_ha)[i * 16 + sl] = r;
        } else {
            float f = di * INV_SCALE;
            float4 o;
            o.x = fmaxf(fmaf(acc.x, f, bb.x), 0.f);
            o.y = fmaxf(fmaf(acc.y, f, bb.y), 0.f);
            o.z = fmaxf(fmaf(acc.z, f, bb.z), 0.f);
            o.w = fmaxf(fmaf(acc.w, f, bb.w), 0.f);
            ((float4*)g_xf)[i * 16 + sl] = o;
        }
    }
}

// ---------------- pool (mean+max) + classifier, one block per graph ----------------
__device__ void pool_cls(const int* __restrict__ batch,
                         const float* __restrict__ Wc1, const float* __restrict__ bc1,
                         const float* __restrict__ Wc2, const float* __restrict__ bc2,
                         float* __restrict__ out, char* sm) {
    int g = blockIdx.x;
    int lo = 0, hi = Nn;
    while (lo < hi) { int m = (lo + hi) >> 1; if (batch[m] < g) lo = m + 1; else hi = m; }
    int start = lo;
    hi = Nn;
    while (lo < hi) { int m = (lo + hi) >> 1; if (batch[m] < g + 1) lo = m + 1; else hi = m; }
    int end = lo;

    int warp = threadIdx.x >> 5, lane = threadIdx.x & 31;
    const float2* __restrict__ x2 = (const float2*)g_xf;
    float2 s  = make_float2(0.f, 0.f);
    float2 mx = make_float2(0.f, 0.f);
    for (int i = start + warp; i < end; i += 8) {
        float2 v = x2[i * 32 + lane];
        s.x += v.x; s.y += v.y;
        mx.x = fmaxf(mx.x, v.x); mx.y = fmaxf(mx.y, v.y);
    }
    float*  hs  = (float*)sm;                      // [128]
    float2* ss  = (float2*)(sm + 512);             // [8][32]
    float2* sm2 = (float2*)(sm + 512 + 2048);      // [8][32]
    float*  hid = (float*)(sm + 512 + 4096);       // [64]
    ss[warp * 32 + lane] = s;
    sm2[warp * 32 + lane] = mx;
    __syncthreads();
    if (warp == 0) {
        for (int w = 1; w < 8; w++) {
            float2 a = ss[w * 32 + lane], m = sm2[w * 32 + lane];
            s.x += a.x; s.y += a.y;
            mx.x = fmaxf(mx.x, m.x); mx.y = fmaxf(mx.y, m.y);
        }
        float inv = 1.f / fmaxf((float)(end - start), 1.f);
        hs[2 * lane]          = s.x * inv;
        hs[2 * lane + 1]      = s.y * inv;
        hs[64 + 2 * lane]     = mx.x;
        hs[64 + 2 * lane + 1] = mx.y;
    }
    __syncthreads();
    int j = threadIdx.x;
    if (j < 64) {
        float acc = bc1[j];
#pragma unroll
        for (int k = 0; k < 128; k++)
            acc = fmaf(hs[k], Wc1[k * 64 + j], acc);
        hid[j] = fmaxf(acc, 0.f);
    }
    __syncthreads();
    if (j < 2) {
        float a = bc2[j];
#pragma unroll
        for (int k = 0; k < 64; k++)
            a = fmaf(hid[k], Wc2[k * 2 + j], a);
        out[g * 2 + j] = a;
    }
    __syncthreads();
}

// ---------------- the one persistent kernel ----------------
__global__ void __launch_bounds__(NT, 4) k_all(
    const int* __restrict__ tok, const int* __restrict__ ei,
    const int* __restrict__ batch, const float* __restrict__ emb,
    const float* __restrict__ W0, const float* __restrict__ b0,
    const float* __restrict__ W1, const float* __restrict__ b1,
    const float* __restrict__ W2, const float* __restrict__ b2,
    const float* __restrict__ Wc1, const float* __restrict__ bc1,
    const float* __restrict__ Wc2, const float* __restrict__ bc2,
    float* __restrict__ out)
{
    __shared__ __align__(16) char smbuf[34816];
    unsigned ls = 0;
    int tid = threadIdx.x;
    int gtid = blockIdx.x * NT + tid;
    const int4* src4 = (const int4*)ei;
    const int4* dst4 = (const int4*)(ei + Ee);

    // ---- P1: embed + degree-hist (independent) + W->fp16 + sentinel zero ----
    // g_deg is zero on entry (zero-init at load; end-phase cleanup each launch)
    for (int t = gtid; t < Nn * 16; t += GT) {
        int i = t >> 4;
        float4 v = ((const float4*)emb)[tok[i] * 16 + (t & 15)];
        __half2 h0 = __floats2half2_rn(v.x * SCALE, v.y * SCALE);
        __half2 h1 = __floats2half2_rn(v.z * SCALE, v.w * SCALE);
        ((__half2*)g_ha)[2 * t]     = h0;
        ((__half2*)g_ha)[2 * t + 1] = h1;
    }
    for (int e = gtid; e < Ee / 4; e += GT) {
        int4 d = dst4[e];
        atomicAdd(&g_deg[d.x], 1);
        atomicAdd(&g_deg[d.y], 1);
        atomicAdd(&g_deg[d.z], 1);
        atomicAdd(&g_deg[d.w], 1);
    }
    if (blockIdx.x == NB - 1)
        for (int t = tid; t < Dd * Dd; t += NT) g_w[0][t] = __float2half(W0[t]);
    if (blockIdx.x == NB - 2)
        for (int t = tid; t < Dd * Dd; t += NT) g_w[1][t] = __float2half(W1[t]);
    if (blockIdx.x == NB - 3)
        for (int t = tid; t < Dd * Dd; t += NT) g_w[2][t] = __float2half(W2[t]);
    if (blockIdx.x == 0 && tid < 8)
        ((uint4*)(g_hb + Nn * Dd))[tid] = make_uint4(0u, 0u, 0u, 0u);
    gsync(ls);   // 1

    // ---- P2: row allocation (padded to 8) + dinv + sentinel pad fill ----
    for (int i = gtid; i < Nn; i += GT) {
        int d  = g_deg[i];
        int dp = (d + 7) & ~7;
        int rs = atomicAdd(&g_counter, dp);
        g_rowstart[i] = rs;
        g_cursor[i]   = rs;
        g_dinv[i]     = rsqrtf((float)(d + 1));
        g_deg[i]      = dp;                       // store padded count
        for (int p = rs + d; p < rs + dp; p++) g_col[p] = Nn;
    }
    gsync(ls);   // 2

    // ---- P3: scatter (444 blocks) CONCURRENT with gemm0 (148 blocks) ----
    if (blockIdx.x < P4_GEMM_BLKS) {
        gemm_phase(g_w[0], blockIdx.x, P4_GEMM_BLKS, smbuf);
    } else {
        int lt = (blockIdx.x - P4_GEMM_BLKS) * NT + tid;
        int LS = (NB - P4_GEMM_BLKS) * NT;
        for (int e = lt; e < Ee / 4; e += LS) {
            int4 s = src4[e];
            int4 d = dst4[e];
            g_col[atomicAdd(&g_cursor[d.x], 1)] = s.x;
            g_col[atomicAdd(&g_cursor[d.y], 1)] = s.y;
            g_col[atomicAdd(&g_cursor[d.z], 1)] = s.z;
            g_col[atomicAdd(&g_cursor[d.w], 1)] = s.w;
        }
    }
    gsync(ls);   // 3

    aggr_phase(b0, 0);                          gsync(ls);   // 4
    gemm_phase(g_w[1], blockIdx.x, NB, smbuf);  gsync(ls);   // 5
    aggr_phase(b1, 0);                          gsync(ls);   // 6
    gemm_phase(g_w[2], blockIdx.x, NB, smbuf);  gsync(ls);   // 7
    aggr_phase(b2, 1);                          gsync(ls);   // 8 (even -> sense back to 0)

    // ---- final: pool+cls on blocks <Gg; state cleanup on the rest ----
    if (blockIdx.x < Gg) {
        pool_cls(batch, Wc1, bc1, Wc2, bc2, out, smbuf);
    } else {
        int ct = (blockIdx.x - Gg) * NT + tid;
        int CS = (NB - Gg) * NT;
        for (int i = ct; i < Nn; i += CS) g_deg[i] = 0;
        if (blockIdx.x == Gg && tid == 0) g_counter = 0;
    }
}

extern "C" void kernel_launch(void* const* d_in, const int* in_sizes, int n_in,
                              void* d_out, int out_size) {
    const int*   tok   = (const int*)d_in[0];
    const int*   ei    = (const int*)d_in[1];
    const int*   batch = (const int*)d_in[2];
    const float* emb   = (const float*)d_in[3];
    const float* W0 = (const float*)d_in[4];  const float* b0 = (const float*)d_in[5];
    const float* W1 = (const float*)d_in[6];  const float* b1 = (const float*)d_in[7];
    const float* W2 = (const float*)d_in[8];  const float* b2 = (const float*)d_in[9];
    const float* Wc1 = (const float*)d_in[10]; const float* bc1 = (const float*)d_in[11];
    const float* Wc2 = (const float*)d_in[12]; const float* bc2 = (const float*)d_in[13];
    float* out = (float*)d_out;

    k_all<<<NB, NT>>>(tok, ei, batch, emb, W0, b0, W1, b1, W2, b2,
                      Wc1, bc1, Wc2, bc2, out);
}